// round 11
// baseline (speedup 1.0000x reference)
#include <cuda_runtime.h>
#include <cuda_bf16.h>
#include <cstdint>

// Problem constants
#define BB 4
#define SS 2048
#define DD 1024
#define HH 16
#define DHH 64
#define MROWS (BB * SS)          // 8192
#define SCALE2 0.1803368801111204f   // DH^-0.5 * log2(e)

// ---------------------------------------------------------------------------
// Scratch (allocation-free rule: device globals) — bf16 hi/lo pairs
// ---------------------------------------------------------------------------
__device__ __nv_bfloat16 g_Xhi[3][MROWS * DD];   // split x_q, x_k, x_v
__device__ __nv_bfloat16 g_Xlo[3][MROWS * DD];
__device__ __nv_bfloat16 g_Whi[4][DD * DD];      // split W^T [N,K]: q,k,v,o
__device__ __nv_bfloat16 g_Wlo[4][DD * DD];
__device__ __nv_bfloat16 g_Qhi[BB * HH * SS * DHH];   // [B,H,S,DH]
__device__ __nv_bfloat16 g_Qlo[BB * HH * SS * DHH];
__device__ __nv_bfloat16 g_Khi[BB * HH * SS * DHH];
__device__ __nv_bfloat16 g_Klo[BB * HH * SS * DHH];
__device__ __nv_bfloat16 g_Vhi[BB * HH * SS * DHH];
__device__ __nv_bfloat16 g_Vlo[BB * HH * SS * DHH];
__device__ __nv_bfloat16 g_Ahi[MROWS * DD];      // attention out [B,S,H*DH]
__device__ __nv_bfloat16 g_Alo[MROWS * DD];

// ---------------------------------------------------------------------------
// Baseline-PTX helpers (no sm_103a-only features)
// ---------------------------------------------------------------------------
__device__ __forceinline__ uint32_t smem_u32(const void* p) {
    uint32_t a;
    asm("{ .reg .u64 t; cvta.to.shared.u64 t, %1; cvt.u32.u64 %0, t; }"
        : "=r"(a) : "l"(p));
    return a;
}
#define CP_ASYNC16(dst, src) \
    asm volatile("cp.async.cg.shared.global [%0], [%1], 16;" :: "r"(dst), "l"(src))
#define CP_COMMIT() asm volatile("cp.async.commit_group;" ::: "memory")
#define CP_WAIT(n)  asm volatile("cp.async.wait_group %0;" :: "n"(n) : "memory")

__device__ __forceinline__ void ldmx4(uint32_t* r, uint32_t addr) {
    asm volatile("ldmatrix.sync.aligned.m8n8.x4.shared.b16 {%0,%1,%2,%3}, [%4];"
                 : "=r"(r[0]), "=r"(r[1]), "=r"(r[2]), "=r"(r[3]) : "r"(addr));
}
__device__ __forceinline__ void ldmx4t(uint32_t* r, uint32_t addr) {
    asm volatile("ldmatrix.sync.aligned.m8n8.x4.trans.shared.b16 {%0,%1,%2,%3}, [%4];"
                 : "=r"(r[0]), "=r"(r[1]), "=r"(r[2]), "=r"(r[3]) : "r"(addr));
}
__device__ __forceinline__ void mma16816(float* d, const uint32_t* a,
                                         uint32_t b0, uint32_t b1) {
    asm volatile(
        "mma.sync.aligned.m16n8k16.row.col.f32.bf16.bf16.f32 "
        "{%0,%1,%2,%3}, {%4,%5,%6,%7}, {%8,%9}, {%0,%1,%2,%3};"
        : "+f"(d[0]), "+f"(d[1]), "+f"(d[2]), "+f"(d[3])
        : "r"(a[0]), "r"(a[1]), "r"(a[2]), "r"(a[3]), "r"(b0), "r"(b1));
}
__device__ __forceinline__ uint32_t b2u(__nv_bfloat162 v) { return *(uint32_t*)&v; }
__device__ __forceinline__ float ex2(float x) {
    float y;
    asm("ex2.approx.f32 %0, %1;" : "=f"(y) : "f"(x));
    return y;
}

// ---------------------------------------------------------------------------
// Conversion kernels (fp32 -> bf16 hi/lo split), batched over grid.z
// ---------------------------------------------------------------------------
__global__ void __launch_bounds__(256)
conv_hl3(const float* __restrict__ x0, const float* __restrict__ x1,
         const float* __restrict__ x2, int n4) {
    const int z = blockIdx.z;
    const float* x = (z == 0) ? x0 : (z == 1) ? x1 : x2;
    __nv_bfloat16* hi = g_Xhi[z];
    __nv_bfloat16* lo = g_Xlo[z];
    int i = blockIdx.x * blockDim.x + threadIdx.x;
    if (i >= n4) return;
    float4 v = ((const float4*)x)[i];
    __nv_bfloat16 h0 = __float2bfloat16(v.x);
    __nv_bfloat16 h1 = __float2bfloat16(v.y);
    __nv_bfloat16 h2 = __float2bfloat16(v.z);
    __nv_bfloat16 h3 = __float2bfloat16(v.w);
    __nv_bfloat16 l0 = __float2bfloat16(v.x - __bfloat162float(h0));
    __nv_bfloat16 l1 = __float2bfloat16(v.y - __bfloat162float(h1));
    __nv_bfloat16 l2 = __float2bfloat16(v.z - __bfloat162float(h2));
    __nv_bfloat16 l3 = __float2bfloat16(v.w - __bfloat162float(h3));
    ((__nv_bfloat162*)hi)[2 * i]     = __nv_bfloat162(h0, h1);
    ((__nv_bfloat162*)hi)[2 * i + 1] = __nv_bfloat162(h2, h3);
    ((__nv_bfloat162*)lo)[2 * i]     = __nv_bfloat162(l0, l1);
    ((__nv_bfloat162*)lo)[2 * i + 1] = __nv_bfloat162(l2, l3);
}

// W [K,N] row-major -> g_W{hi,lo}[z][n][k] = split(W[k][n]); grid.z = 4
__global__ void __launch_bounds__(256)
convT4(const float* __restrict__ W0, const float* __restrict__ W1,
       const float* __restrict__ W2, const float* __restrict__ W3) {
    const int z = blockIdx.z;
    const float* W = (z == 0) ? W0 : (z == 1) ? W1 : (z == 2) ? W2 : W3;
    __nv_bfloat16* hi = g_Whi[z];
    __nv_bfloat16* lo = g_Wlo[z];
    __shared__ float ts[32][33];
    const int tx = threadIdx.x, ty = threadIdx.y;  // 32 x 8
    const int n0 = blockIdx.x * 32, k0 = blockIdx.y * 32;
#pragma unroll
    for (int i = 0; i < 4; i++)
        ts[ty + i * 8][tx] = W[(size_t)(k0 + ty + i * 8) * DD + n0 + tx];
    __syncthreads();
#pragma unroll
    for (int i = 0; i < 4; i++) {
        float v = ts[tx][ty + i * 8];
        __nv_bfloat16 h = __float2bfloat16(v);
        __nv_bfloat16 l = __float2bfloat16(v - __bfloat162float(h));
        size_t o = (size_t)(n0 + ty + i * 8) * DD + k0 + tx;
        hi[o] = h;
        lo[o] = l;
    }
}

// ---------------------------------------------------------------------------
// HMMA split-bf16 GEMM, big warp tiles: CTA 128(M)x256(N), BK=32, 8 warps
// in 2(m)x4(n), warp tile 64x64 (acc 128 regs). MMA:LDSM = 6:1 -> MMA-bound.
// 2-stage cp.async, single barrier/iter (wait -> sync -> compute/issue).
// ---------------------------------------------------------------------------
#define ROWB 80                         // bytes per smem row (32 bf16 + pad)
#define A_MAT 10240                     // 128 rows * 80
#define B_MAT 20480                     // 256 rows * 80
#define OFF_AH 0
#define OFF_AL (OFF_AH + A_MAT)
#define OFF_BH (OFF_AL + A_MAT)         // 20480
#define OFF_BL (OFF_BH + B_MAT)         // 40960
#define STG_B  (OFF_BL + B_MAT)         // 61440
#define GEMM_SMEM (2 * STG_B)           // 122880

__device__ __forceinline__ void gemm_mainloop(
    uint32_t sb, int tid, int lane, int warp_m, int warp_n,
    const __nv_bfloat16* gAh, const __nv_bfloat16* gAl,
    const __nv_bfloat16* gBh, const __nv_bfloat16* gBl,
    float acc[4][8][4]) {

    // 3072 16B-chunks per stage: A_hi 512, A_lo 512, B_hi 1024, B_lo 1024
    auto issue_stage = [&](int stg, int kt) {
        const uint32_t base = sb + stg * STG_B;
#pragma unroll
        for (int j = 0; j < 12; j++) {
            const int id = tid + j * 256;
            uint32_t moff;
            const __nv_bfloat16* src;
            int cid;
            if (j < 2)      { moff = OFF_AH; src = gAh; cid = id; }
            else if (j < 4) { moff = OFF_AL; src = gAl; cid = id - 512; }
            else if (j < 8) { moff = OFF_BH; src = gBh; cid = id - 1024; }
            else            { moff = OFF_BL; src = gBl; cid = id - 2048; }
            const int r = cid >> 2, c = cid & 3;
            CP_ASYNC16(base + moff + r * ROWB + c * 16,
                       src + (size_t)r * DD + kt + c * 8);
        }
        CP_COMMIT();
    };

    auto compute_ks = [&](uint32_t base, int ks) {
        const uint32_t koff = (ks * 16 + (lane >> 4) * 8) * 2;
        uint32_t a_hi[4][4], a_lo[4][4];
        const int arow = warp_m * 64 + (lane & 15);
#pragma unroll
        for (int mt = 0; mt < 4; mt++) {
            const uint32_t ro = (uint32_t)(arow + mt * 16) * ROWB + koff;
            ldmx4(a_hi[mt], base + OFF_AH + ro);
            ldmx4(a_lo[mt], base + OFF_AL + ro);
        }
        const int brow = warp_n * 64 + (lane & 15);
#pragma unroll
        for (int ntp = 0; ntp < 2; ntp++) {
            uint32_t b_hi[2][4], b_lo[2][4];
#pragma unroll
            for (int j = 0; j < 2; j++) {
                const uint32_t ro =
                    (uint32_t)(brow + (ntp * 2 + j) * 16) * ROWB + koff;
                ldmx4(b_hi[j], base + OFF_BH + ro);
                ldmx4(b_lo[j], base + OFF_BL + ro);
            }
            // product-major order: same-acc reuse distance = 16 MMAs
#pragma unroll
            for (int p = 0; p < 3; p++) {
#pragma unroll
                for (int j = 0; j < 2; j++) {
                    const int nt = ntp * 2 + j;
                    const uint32_t* bb = (p == 1) ? b_lo[j] : b_hi[j];
#pragma unroll
                    for (int mt = 0; mt < 4; mt++) {
                        const uint32_t* aa = (p == 2) ? a_lo[mt] : a_hi[mt];
                        mma16816(acc[mt][nt * 2 + 0], aa, bb[0], bb[2]);
                        mma16816(acc[mt][nt * 2 + 1], aa, bb[1], bb[3]);
                    }
                }
            }
        }
    };

    issue_stage(0, 0);

#pragma unroll 1
    for (int it = 0; it < 32; it++) {
        CP_WAIT(0);                    // own part of group 'it' landed
        __syncthreads();               // publish all writes (RAW) + WAR guard
        const uint32_t base = sb + (it & 1) * STG_B;
        compute_ks(base, 0);           // MMAs start right after barrier
        if (it + 1 < 32)
            issue_stage((it + 1) & 1, (it + 1) * 32);  // overlaps compute
        compute_ks(base, 1);
    }
}

// QKV projections in one launch: grid.z selects (X, W, dest)
__global__ void __launch_bounds__(256, 1)
gemm_qkv() {
    extern __shared__ char smem[];
    const uint32_t sb = smem_u32(smem);
    const int tid = threadIdx.x;
    const int wid = tid >> 5;
    const int lane = tid & 31;
    const int warp_m = wid & 1;        // 2 warps along M (64 rows)
    const int warp_n = wid >> 1;       // 4 warps along N (64 cols)
    const int m0 = blockIdx.y * 128;
    const int n0 = blockIdx.x * 256;
    const int z = blockIdx.z;

    __nv_bfloat16* outH = (z == 0) ? g_Qhi : (z == 1) ? g_Khi : g_Vhi;
    __nv_bfloat16* outL = (z == 0) ? g_Qlo : (z == 1) ? g_Klo : g_Vlo;

    float acc[4][8][4];
#pragma unroll
    for (int i = 0; i < 4; i++)
#pragma unroll
        for (int j = 0; j < 8; j++)
#pragma unroll
            for (int q = 0; q < 4; q++) acc[i][j][q] = 0.f;

    gemm_mainloop(sb, tid, lane, warp_m, warp_n,
                  g_Xhi[z] + (size_t)m0 * DD, g_Xlo[z] + (size_t)m0 * DD,
                  g_Whi[z] + (size_t)n0 * DD, g_Wlo[z] + (size_t)n0 * DD, acc);

    // Q is pre-scaled by SCALE2 (softmax scale folded, exact pre-split)
    const float osc = (z == 0) ? SCALE2 : 1.0f;

    // epilogue: bf16 hi/lo into [B,H,S,DH]
#pragma unroll
    for (int mt = 0; mt < 4; mt++) {
#pragma unroll
        for (int nt = 0; nt < 8; nt++) {
            const int r = m0 + warp_m * 64 + mt * 16 + (lane >> 2);
            const int n_abs = n0 + warp_n * 64 + nt * 8 + (lane & 3) * 2;
            const int h = n_abs >> 6, dh = n_abs & 63;
#pragma unroll
            for (int half = 0; half < 2; half++) {
                const int rr = r + half * 8;
                const int b1 = rr >> 11, s1 = rr & (SS - 1);
                const size_t o = ((((size_t)(b1 * HH + h)) * SS + s1) << 6) + dh;
                float2 v = make_float2(acc[mt][nt][half * 2] * osc,
                                       acc[mt][nt][half * 2 + 1] * osc);
                __nv_bfloat162 hv = __float22bfloat162_rn(v);
                float2 hf = __bfloat1622float2(hv);
                __nv_bfloat162 lv = __float22bfloat162_rn(
                    make_float2(v.x - hf.x, v.y - hf.y));
                *(__nv_bfloat162*)(outH + o) = hv;
                *(__nv_bfloat162*)(outL + o) = lv;
            }
        }
    }
}

// Final projection: A = attention out (hi/lo), B = Wo, fp32 row-major out
__global__ void __launch_bounds__(256, 1)
gemm_out(float* __restrict__ outF) {
    extern __shared__ char smem[];
    const uint32_t sb = smem_u32(smem);
    const int tid = threadIdx.x;
    const int wid = tid >> 5;
    const int lane = tid & 31;
    const int warp_m = wid & 1;
    const int warp_n = wid >> 1;
    const int m0 = blockIdx.y * 128;
    const int n0 = blockIdx.x * 256;

    float acc[4][8][4];
#pragma unroll
    for (int i = 0; i < 4; i++)
#pragma unroll
        for (int j = 0; j < 8; j++)
#pragma unroll
            for (int q = 0; q < 4; q++) acc[i][j][q] = 0.f;

    gemm_mainloop(sb, tid, lane, warp_m, warp_n,
                  g_Ahi + (size_t)m0 * DD, g_Alo + (size_t)m0 * DD,
                  g_Whi[3] + (size_t)n0 * DD, g_Wlo[3] + (size_t)n0 * DD, acc);

#pragma unroll
    for (int mt = 0; mt < 4; mt++) {
#pragma unroll
        for (int nt = 0; nt < 8; nt++) {
            const int r = m0 + warp_m * 64 + mt * 16 + (lane >> 2);
            const int n_abs = n0 + warp_n * 64 + nt * 8 + (lane & 3) * 2;
            float* d0 = outF + (size_t)r * DD + n_abs;
            *(float2*)d0 = make_float2(acc[mt][nt][0], acc[mt][nt][1]);
            float* d1 = outF + (size_t)(r + 8) * DD + n_abs;
            *(float2*)d1 = make_float2(acc[mt][nt][2], acc[mt][nt][3]);
        }
    }
}

// ---------------------------------------------------------------------------
// HMMA split-bf16 flash attention (unchanged from R10): CTA = 128 Q rows x
// one (b,h); 8 warps; KV tiles of 64; 3-stage cp.async pipeline; Q staged
// through stage 2; heavy-first scheduling; Q pre-scaled by SCALE2.
// ---------------------------------------------------------------------------
#define FROWB 144                         // 64 bf16 = 128B data + 16B pad
#define QTILE_B (128 * FROWB)             // 18432 per matrix (hi or lo)
#define KV_MAT_B (64 * FROWB)             // 9216
#define KV_STG_B (4 * KV_MAT_B)           // 36864
#define FLASH_SMEM (3 * KV_STG_B)         // 110592

__global__ void __launch_bounds__(256, 2)
flash_tc() {
    extern __shared__ char smem[];
    const uint32_t skv = smem_u32(smem);
    const uint32_t sq = skv + 2 * KV_STG_B;   // Q staged in stage-2 region
    const int tid = threadIdx.x, wid = tid >> 5, lane = tid & 31;
    const int bh = blockIdx.x;
    const int qt = (int)gridDim.y - 1 - blockIdx.y;   // heavy tiles first
    const int q0 = qt * 128;
    const size_t base = (size_t)bh * SS * DHH;

    // ---- Q tile load into stage-2 region [group 0]
    {
        const int mat = tid >> 7;              // 0: hi, 1: lo
        const int r = tid & 127;
        const __nv_bfloat16* src =
            (mat == 0 ? g_Qhi : g_Qlo) + base + (size_t)(q0 + r) * 64;
        const uint32_t dst = sq + mat * QTILE_B + r * FROWB;
#pragma unroll
        for (int j = 0; j < 8; j++) CP_ASYNC16(dst + j * 16, src + j * 8);
    }
    CP_COMMIT();

    // ---- KV stage issue: thread owns one row of one matrix
    const int kvmat = tid >> 6;                // 0..3: Khi,Klo,Vhi,Vlo
    const int kvr = tid & 63;
    const __nv_bfloat16* kvsrc =
        (kvmat == 0 ? g_Khi : kvmat == 1 ? g_Klo : kvmat == 2 ? g_Vhi : g_Vlo)
        + base;
    auto issue_kv = [&](int stg, int jt) {
        const uint32_t dst = skv + stg * KV_STG_B + kvmat * KV_MAT_B + kvr * FROWB;
        const __nv_bfloat16* src = kvsrc + (size_t)(jt * 64 + kvr) * 64;
#pragma unroll
        for (int j = 0; j < 8; j++) CP_ASYNC16(dst + j * 16, src + j * 8);
        CP_COMMIT();
    };
    const int jt_max = 2 * qt + 1;             // >= 1 always
    issue_kv(0, 0);                            // [group 1]
    issue_kv(1, 1);                            // [group 2]
    CP_WAIT(2);                                // Q (oldest group) landed
    __syncthreads();                           // all threads' Q writes visible

    // ---- Q fragments (per warp: 16 rows x 64 dims, hi+lo)
    uint32_t qh[4][4], ql[4][4];
    {
        const uint32_t ra = sq + (uint32_t)(wid * 16 + (lane & 15)) * FROWB
                          + (lane >> 4) * 16;
#pragma unroll
        for (int ks = 0; ks < 4; ks++) {
            ldmx4(qh[ks], ra + ks * 32);
            ldmx4(ql[ks], ra + QTILE_B + ks * 32);
        }
    }
    // No extra barrier: jt=0's barrier orders all warps' Q extraction before
    // the first issue into stage 2 (kv tile 2, issued in the jt=0 body).

    float oacc[8][4];
#pragma unroll
    for (int i = 0; i < 8; i++)
#pragma unroll
        for (int q = 0; q < 4; q++) oacc[i][q] = 0.f;
    float mrow0 = -INFINITY, mrow1 = -INFINITY, lrow0 = 0.f, lrow1 = 0.f;
    const int grow0 = q0 + wid * 16 + (lane >> 2);

#pragma unroll 1
    for (int jt = 0; jt <= jt_max; jt++) {
        if (jt < jt_max) CP_WAIT(1);           // stage jt landed
        else             CP_WAIT(0);
        __syncthreads();                       // publish (RAW) + WAR guard

        const uint32_t kb = skv + (jt % 3) * KV_STG_B;

        // ---- S = Q K^T (16 x 64 per warp), 3-product split
        float s[8][4];
#pragma unroll
        for (int i = 0; i < 8; i++)
#pragma unroll
            for (int q = 0; q < 4; q++) s[i][q] = 0.f;
#pragma unroll
        for (int ks = 0; ks < 4; ks++) {
            const uint32_t ka = kb + (uint32_t)(lane & 15) * FROWB
                              + (lane >> 4) * 16 + ks * 32;
#pragma unroll
            for (int ntp = 0; ntp < 2; ntp++) {
                uint32_t bh_[2][4], bl_[2][4];
#pragma unroll
                for (int j = 0; j < 2; j++) {
                    const uint32_t ro = ka + (ntp * 2 + j) * 16 * FROWB;
                    ldmx4(bh_[j], ro);
                    ldmx4(bl_[j], ro + KV_MAT_B);
                }
#pragma unroll
                for (int p = 0; p < 3; p++) {
                    const uint32_t* aa = (p == 2) ? ql[ks] : qh[ks];
#pragma unroll
                    for (int j = 0; j < 2; j++) {
                        const int nt2 = ntp * 2 + j;
                        const uint32_t* bb = (p == 1) ? bl_[j] : bh_[j];
                        mma16816(s[nt2 * 2 + 0], aa, bb[0], bb[2]);
                        mma16816(s[nt2 * 2 + 1], aa, bb[1], bb[3]);
                    }
                }
            }
        }

        // ---- prefetch kv(jt+2): LDGSTS overlaps softmax ALU below
        if (jt + 2 <= jt_max) issue_kv((jt + 2) % 3, jt + 2);

        // ---- causal mask (partial-overlap tiles only; scale pre-folded)
        if (jt * 64 + 63 > q0 + wid * 16) {
#pragma unroll
            for (int nt = 0; nt < 8; nt++) {
                const int colb = jt * 64 + nt * 8 + 2 * (lane & 3);
#pragma unroll
                for (int q = 0; q < 4; q++) {
                    const int col = colb + (q & 1);
                    const int row = grow0 + ((q >> 1) << 3);
                    if (col > row) s[nt][q] = -1e30f;
                }
            }
        }

        // ---- online softmax, base-2 (rows r and r+8 per thread)
        float mx0 = -INFINITY, mx1 = -INFINITY;
#pragma unroll
        for (int nt = 0; nt < 8; nt++) {
            mx0 = fmaxf(mx0, fmaxf(s[nt][0], s[nt][1]));
            mx1 = fmaxf(mx1, fmaxf(s[nt][2], s[nt][3]));
        }
        mx0 = fmaxf(mx0, __shfl_xor_sync(0xffffffffu, mx0, 1));
        mx0 = fmaxf(mx0, __shfl_xor_sync(0xffffffffu, mx0, 2));
        mx1 = fmaxf(mx1, __shfl_xor_sync(0xffffffffu, mx1, 1));
        mx1 = fmaxf(mx1, __shfl_xor_sync(0xffffffffu, mx1, 2));
        const float mn0 = fmaxf(mrow0, mx0);
        const float mn1 = fmaxf(mrow1, mx1);
        const float c0 = ex2(mrow0 - mn0);
        const float c1 = ex2(mrow1 - mn1);
        float sum0 = 0.f, sum1 = 0.f;
#pragma unroll
        for (int nt = 0; nt < 8; nt++) {
            s[nt][0] = ex2(s[nt][0] - mn0);
            s[nt][1] = ex2(s[nt][1] - mn0);
            s[nt][2] = ex2(s[nt][2] - mn1);
            s[nt][3] = ex2(s[nt][3] - mn1);
            sum0 += s[nt][0] + s[nt][1];
            sum1 += s[nt][2] + s[nt][3];
        }
        sum0 += __shfl_xor_sync(0xffffffffu, sum0, 1);
        sum0 += __shfl_xor_sync(0xffffffffu, sum0, 2);
        sum1 += __shfl_xor_sync(0xffffffffu, sum1, 1);
        sum1 += __shfl_xor_sync(0xffffffffu, sum1, 2);
        lrow0 = lrow0 * c0 + sum0;  mrow0 = mn0;
        lrow1 = lrow1 * c1 + sum1;  mrow1 = mn1;
#pragma unroll
        for (int nt = 0; nt < 8; nt++) {
            oacc[nt][0] *= c0;  oacc[nt][1] *= c0;
            oacc[nt][2] *= c1;  oacc[nt][3] *= c1;
        }

        // ---- O += P V, P->bf16 hi/lo on the fly, product-major order
#pragma unroll
        for (int ks = 0; ks < 4; ks++) {
            uint32_t ahi[4], alo[4];
#pragma unroll
            for (int hh = 0; hh < 2; hh++) {
                const int nt = 2 * ks + hh;
#pragma unroll
                for (int half = 0; half < 2; half++) {
                    float2 v = make_float2(s[nt][half * 2],
                                           s[nt][half * 2 + 1]);
                    __nv_bfloat162 hv = __float22bfloat162_rn(v);
                    float2 hf = __bfloat1622float2(hv);
                    __nv_bfloat162 lv = __float22bfloat162_rn(
                        make_float2(v.x - hf.x, v.y - hf.y));
                    ahi[hh * 2 + half] = b2u(hv);
                    alo[hh * 2 + half] = b2u(lv);
                }
            }
            const uint32_t va = kb + 2 * KV_MAT_B
                              + (uint32_t)(ks * 16 + (lane & 15)) * FROWB
                              + (lane >> 4) * 16;
#pragma unroll
            for (int ntp = 0; ntp < 2; ntp++) {
                uint32_t vh[2][4], vl[2][4];
#pragma unroll
                for (int j = 0; j < 2; j++) {
                    ldmx4t(vh[j], va + (ntp * 2 + j) * 32);
                    ldmx4t(vl[j], va + KV_MAT_B + (ntp * 2 + j) * 32);
                }
#pragma unroll
                for (int p = 0; p < 3; p++) {
                    const uint32_t* aa = (p == 2) ? alo : ahi;
#pragma unroll
                    for (int j = 0; j < 2; j++) {
                        const int nt2 = ntp * 2 + j;
                        const uint32_t* vv = (p == 1) ? vl[j] : vh[j];
                        mma16816(oacc[2 * nt2 + 0], aa, vv[0], vv[1]);
                        mma16816(oacc[2 * nt2 + 1], aa, vv[2], vv[3]);
                    }
                }
            }
        }
    }

    // ---- epilogue: normalize, split hi/lo, write [B,S,H*DH]
    const float inv0 = 1.f / lrow0, inv1 = 1.f / lrow1;
    const int b = bh >> 4, h = bh & 15;
    const int row0 = b * SS + q0 + wid * 16 + (lane >> 2);
#pragma unroll
    for (int nt = 0; nt < 8; nt++) {
        const int col = h * 64 + nt * 8 + 2 * (lane & 3);
#pragma unroll
        for (int half = 0; half < 2; half++) {
            const float inv = half ? inv1 : inv0;
            float2 v = make_float2(oacc[nt][half * 2] * inv,
                                   oacc[nt][half * 2 + 1] * inv);
            __nv_bfloat162 hv = __float22bfloat162_rn(v);
            float2 hf = __bfloat1622float2(hv);
            __nv_bfloat162 lv = __float22bfloat162_rn(
                make_float2(v.x - hf.x, v.y - hf.y));
            const size_t o = (size_t)(row0 + half * 8) * DD + col;
            *(__nv_bfloat162*)(g_Ahi + o) = hv;
            *(__nv_bfloat162*)(g_Alo + o) = lv;
        }
    }
}

// ---------------------------------------------------------------------------
extern "C" void kernel_launch(void* const* d_in, const int* in_sizes, int n_in,
                              void* d_out, int out_size) {
    (void)in_sizes; (void)n_in; (void)out_size;
    const float* x_q = (const float*)d_in[0];
    const float* x_k = (const float*)d_in[1];
    const float* x_v = (const float*)d_in[2];
    // d_in[3] = mask: deterministic causal triu — handled analytically.
    const float* Wq = (const float*)d_in[4];
    const float* Wk = (const float*)d_in[5];
    const float* Wv = (const float*)d_in[6];
    const float* Wo = (const float*)d_in[7];
    float* out = (float*)d_out;

    static int attr_set = 0;
    if (!attr_set) {
        cudaFuncSetAttribute(flash_tc,
                             cudaFuncAttributeMaxDynamicSharedMemorySize, FLASH_SMEM);
        cudaFuncSetAttribute(gemm_qkv,
                             cudaFuncAttributeMaxDynamicSharedMemorySize, GEMM_SMEM);
        cudaFuncSetAttribute(gemm_out,
                             cudaFuncAttributeMaxDynamicSharedMemorySize, GEMM_SMEM);
        attr_set = 1;
    }

    const int n4 = MROWS * DD / 4;

    // all conversions up front (2 launches)
    convT4<<<dim3(32, 32, 4), dim3(32, 8)>>>(Wq, Wk, Wv, Wo);
    conv_hl3<<<dim3(n4 / 256, 1, 3), 256>>>(x_q, x_k, x_v, n4);

    // Q,K,V projections in one launch (Q pre-scaled by SCALE2)
    gemm_qkv<<<dim3(DD / 256, MROWS / 128, 3), 256, GEMM_SMEM>>>();

    // attention (heavy Q-tiles first; writes hi/lo A for the final GEMM)
    flash_tc<<<dim3(BB * HH, SS / 128), 256, FLASH_SMEM>>>();

    // output projection
    gemm_out<<<dim3(DD / 256, MROWS / 128), 256, GEMM_SMEM>>>(out);
}

// round 12
// speedup vs baseline: 1.1074x; 1.1074x over previous
#include <cuda_runtime.h>
#include <cuda_bf16.h>
#include <cstdint>

// Problem constants
#define BB 4
#define SS 2048
#define DD 1024
#define HH 16
#define DHH 64
#define MROWS (BB * SS)          // 8192
#define SCALE2 0.1803368801111204f   // DH^-0.5 * log2(e)

// ---------------------------------------------------------------------------
// Scratch (allocation-free rule: device globals) — bf16 hi/lo pairs
// ---------------------------------------------------------------------------
__device__ __nv_bfloat16 g_Xhi[3][MROWS * DD];   // split x_q, x_k, x_v
__device__ __nv_bfloat16 g_Xlo[3][MROWS * DD];
__device__ __nv_bfloat16 g_Whi[4][DD * DD];      // split W^T [N,K]: q,k,v,o
__device__ __nv_bfloat16 g_Wlo[4][DD * DD];
__device__ __nv_bfloat16 g_Qhi[BB * HH * SS * DHH];   // [B,H,S,DH]
__device__ __nv_bfloat16 g_Qlo[BB * HH * SS * DHH];
__device__ __nv_bfloat16 g_Khi[BB * HH * SS * DHH];
__device__ __nv_bfloat16 g_Klo[BB * HH * SS * DHH];
__device__ __nv_bfloat16 g_Vhi[BB * HH * SS * DHH];
__device__ __nv_bfloat16 g_Vlo[BB * HH * SS * DHH];
__device__ __nv_bfloat16 g_Ahi[MROWS * DD];      // attention out [B,S,H*DH]
__device__ __nv_bfloat16 g_Alo[MROWS * DD];

// ---------------------------------------------------------------------------
// Baseline-PTX helpers (no sm_103a-only features)
// ---------------------------------------------------------------------------
__device__ __forceinline__ uint32_t smem_u32(const void* p) {
    uint32_t a;
    asm("{ .reg .u64 t; cvta.to.shared.u64 t, %1; cvt.u32.u64 %0, t; }"
        : "=r"(a) : "l"(p));
    return a;
}
#define CP_ASYNC16(dst, src) \
    asm volatile("cp.async.cg.shared.global [%0], [%1], 16;" :: "r"(dst), "l"(src))
#define CP_COMMIT() asm volatile("cp.async.commit_group;" ::: "memory")
#define CP_WAIT(n)  asm volatile("cp.async.wait_group %0;" :: "n"(n) : "memory")

__device__ __forceinline__ void ldmx4(uint32_t* r, uint32_t addr) {
    asm volatile("ldmatrix.sync.aligned.m8n8.x4.shared.b16 {%0,%1,%2,%3}, [%4];"
                 : "=r"(r[0]), "=r"(r[1]), "=r"(r[2]), "=r"(r[3]) : "r"(addr));
}
__device__ __forceinline__ void ldmx4t(uint32_t* r, uint32_t addr) {
    asm volatile("ldmatrix.sync.aligned.m8n8.x4.trans.shared.b16 {%0,%1,%2,%3}, [%4];"
                 : "=r"(r[0]), "=r"(r[1]), "=r"(r[2]), "=r"(r[3]) : "r"(addr));
}
__device__ __forceinline__ void mma16816(float* d, const uint32_t* a,
                                         uint32_t b0, uint32_t b1) {
    asm volatile(
        "mma.sync.aligned.m16n8k16.row.col.f32.bf16.bf16.f32 "
        "{%0,%1,%2,%3}, {%4,%5,%6,%7}, {%8,%9}, {%0,%1,%2,%3};"
        : "+f"(d[0]), "+f"(d[1]), "+f"(d[2]), "+f"(d[3])
        : "r"(a[0]), "r"(a[1]), "r"(a[2]), "r"(a[3]), "r"(b0), "r"(b1));
}
__device__ __forceinline__ uint32_t b2u(__nv_bfloat162 v) { return *(uint32_t*)&v; }
__device__ __forceinline__ float ex2(float x) {
    float y;
    asm("ex2.approx.f32 %0, %1;" : "=f"(y) : "f"(x));
    return y;
}

// ---------------------------------------------------------------------------
// Conversion kernels (fp32 -> bf16 hi/lo split), batched over grid.z
// ---------------------------------------------------------------------------
__global__ void __launch_bounds__(256)
conv_hl3(const float* __restrict__ x0, const float* __restrict__ x1,
         const float* __restrict__ x2, int n4) {
    const int z = blockIdx.z;
    const float* x = (z == 0) ? x0 : (z == 1) ? x1 : x2;
    __nv_bfloat16* hi = g_Xhi[z];
    __nv_bfloat16* lo = g_Xlo[z];
    int i = blockIdx.x * blockDim.x + threadIdx.x;
    if (i >= n4) return;
    float4 v = ((const float4*)x)[i];
    __nv_bfloat16 h0 = __float2bfloat16(v.x);
    __nv_bfloat16 h1 = __float2bfloat16(v.y);
    __nv_bfloat16 h2 = __float2bfloat16(v.z);
    __nv_bfloat16 h3 = __float2bfloat16(v.w);
    __nv_bfloat16 l0 = __float2bfloat16(v.x - __bfloat162float(h0));
    __nv_bfloat16 l1 = __float2bfloat16(v.y - __bfloat162float(h1));
    __nv_bfloat16 l2 = __float2bfloat16(v.z - __bfloat162float(h2));
    __nv_bfloat16 l3 = __float2bfloat16(v.w - __bfloat162float(h3));
    ((__nv_bfloat162*)hi)[2 * i]     = __nv_bfloat162(h0, h1);
    ((__nv_bfloat162*)hi)[2 * i + 1] = __nv_bfloat162(h2, h3);
    ((__nv_bfloat162*)lo)[2 * i]     = __nv_bfloat162(l0, l1);
    ((__nv_bfloat162*)lo)[2 * i + 1] = __nv_bfloat162(l2, l3);
}

// W [K,N] row-major -> g_W{hi,lo}[z][n][k] = split(W[k][n]); grid.z = 4
__global__ void __launch_bounds__(256)
convT4(const float* __restrict__ W0, const float* __restrict__ W1,
       const float* __restrict__ W2, const float* __restrict__ W3) {
    const int z = blockIdx.z;
    const float* W = (z == 0) ? W0 : (z == 1) ? W1 : (z == 2) ? W2 : W3;
    __nv_bfloat16* hi = g_Whi[z];
    __nv_bfloat16* lo = g_Wlo[z];
    __shared__ float ts[32][33];
    const int tx = threadIdx.x, ty = threadIdx.y;  // 32 x 8
    const int n0 = blockIdx.x * 32, k0 = blockIdx.y * 32;
#pragma unroll
    for (int i = 0; i < 4; i++)
        ts[ty + i * 8][tx] = W[(size_t)(k0 + ty + i * 8) * DD + n0 + tx];
    __syncthreads();
#pragma unroll
    for (int i = 0; i < 4; i++) {
        float v = ts[tx][ty + i * 8];
        __nv_bfloat16 h = __float2bfloat16(v);
        __nv_bfloat16 l = __float2bfloat16(v - __bfloat162float(h));
        size_t o = (size_t)(n0 + ty + i * 8) * DD + k0 + tx;
        hi[o] = h;
        lo[o] = l;
    }
}

// ---------------------------------------------------------------------------
// HMMA split-bf16 GEMM (R10 shape): CTA 128x128, BK=32, 2-stage cp.async,
// 8 warps (32x64), single barrier/iter. NEW: manual LDSM/MMA software
// pipelining — b(ntp1) fragments are loaded between the p=0 and p=1 MMA
// groups of ntp0 (asm volatile fixes emission order, so this is the SASS
// order). Peak live regs ~112 -> stays at 2 CTAs/SM.
// ---------------------------------------------------------------------------
#define ROWB 80                       // bytes per smem row
#define ARR_B (128 * ROWB)            // 10240 B per matrix tile
#define STG_B (4 * ARR_B)             // Ahi, Alo, Bhi, Blo = 40960 B
#define GEMM_SMEM (2 * STG_B)         // 81920 B

__device__ __forceinline__ void gemm_mainloop(
    uint32_t sb, int tid, int lane, int warp_m, int warp_n,
    const __nv_bfloat16* gAh, const __nv_bfloat16* gAl,
    const __nv_bfloat16* gBh, const __nv_bfloat16* gBl,
    float acc[2][8][4]) {

    auto issue_stage = [&](int stg, int kt) {
        const uint32_t base = sb + stg * STG_B;
#pragma unroll
        for (int j = 0; j < 2; j++) {
            const int idx = tid + j * 256;
            const int r = idx >> 2;
            const int c8 = idx & 3;
            const uint32_t so = r * ROWB + c8 * 16;
            const size_t go = (size_t)r * DD + kt + c8 * 8;
            CP_ASYNC16(base + 0 * ARR_B + so, gAh + go);
            CP_ASYNC16(base + 1 * ARR_B + so, gAl + go);
            CP_ASYNC16(base + 2 * ARR_B + so, gBh + go);
            CP_ASYNC16(base + 3 * ARR_B + so, gBl + go);
        }
        CP_COMMIT();
    };

    auto compute_ks = [&](uint32_t base, int ks) {
        const uint32_t koff = (ks * 16 + (lane >> 4) * 8) * 2;
        uint32_t a_hi[2][4], a_lo[2][4];
        const int arow = warp_m * 32 + (lane & 15);
#pragma unroll
        for (int mt = 0; mt < 2; mt++) {
            const uint32_t ro = (uint32_t)(arow + mt * 16) * ROWB + koff;
            ldmx4(a_hi[mt], base + 0 * ARR_B + ro);
            ldmx4(a_lo[mt], base + 1 * ARR_B + ro);
        }
        const int brow = warp_n * 64 + (lane & 15);
        const uint32_t b_base2 = base + 2 * ARR_B;
        const uint32_t b_base3 = base + 3 * ARR_B;
        uint32_t b0_h[2][4], b0_l[2][4], b1_h[2][4], b1_l[2][4];
        // load ntp0 B fragments
#pragma unroll
        for (int j = 0; j < 2; j++) {
            const uint32_t ro = (uint32_t)(brow + j * 16) * ROWB + koff;
            ldmx4(b0_h[j], b_base2 + ro);
            ldmx4(b0_l[j], b_base3 + ro);
        }
        // ---- ntp0: p=0 MMAs (hi*hi) first
#pragma unroll
        for (int j = 0; j < 2; j++)
#pragma unroll
            for (int mt = 0; mt < 2; mt++) {
                mma16816(acc[mt][j * 2 + 0], a_hi[mt], b0_h[j][0], b0_h[j][2]);
                mma16816(acc[mt][j * 2 + 1], a_hi[mt], b0_h[j][1], b0_h[j][3]);
            }
        // prefetch ntp1 B fragments (overlaps remaining ntp0 MMAs)
#pragma unroll
        for (int j = 0; j < 2; j++) {
            const uint32_t ro = (uint32_t)(brow + (2 + j) * 16) * ROWB + koff;
            ldmx4(b1_h[j], b_base2 + ro);
            ldmx4(b1_l[j], b_base3 + ro);
        }
        // ---- ntp0: p=1 (hi*lo) and p=2 (lo*hi)
#pragma unroll
        for (int j = 0; j < 2; j++)
#pragma unroll
            for (int mt = 0; mt < 2; mt++) {
                mma16816(acc[mt][j * 2 + 0], a_hi[mt], b0_l[j][0], b0_l[j][2]);
                mma16816(acc[mt][j * 2 + 1], a_hi[mt], b0_l[j][1], b0_l[j][3]);
            }
#pragma unroll
        for (int j = 0; j < 2; j++)
#pragma unroll
            for (int mt = 0; mt < 2; mt++) {
                mma16816(acc[mt][j * 2 + 0], a_lo[mt], b0_h[j][0], b0_h[j][2]);
                mma16816(acc[mt][j * 2 + 1], a_lo[mt], b0_h[j][1], b0_h[j][3]);
            }
        // ---- ntp1: all three products (fragments already resident)
#pragma unroll
        for (int p = 0; p < 3; p++) {
#pragma unroll
            for (int j = 0; j < 2; j++) {
                const int nt = 2 + j;
                const uint32_t* bb = (p == 1) ? b1_l[j] : b1_h[j];
#pragma unroll
                for (int mt = 0; mt < 2; mt++) {
                    const uint32_t* aa = (p == 2) ? a_lo[mt] : a_hi[mt];
                    mma16816(acc[mt][nt * 2 + 0], aa, bb[0], bb[2]);
                    mma16816(acc[mt][nt * 2 + 1], aa, bb[1], bb[3]);
                }
            }
        }
    };

    issue_stage(0, 0);

#pragma unroll 1
    for (int it = 0; it < 32; it++) {
        CP_WAIT(0);                    // own part of group 'it' landed
        __syncthreads();               // publish all writes (RAW) + WAR guard
        const uint32_t base = sb + (it & 1) * STG_B;
        compute_ks(base, 0);           // MMAs start right after barrier
        if (it + 1 < 32)
            issue_stage((it + 1) & 1, (it + 1) * 32);  // overlaps compute
        compute_ks(base, 1);
    }
}

// QKV projections in one launch: grid.z selects (X, W, dest)
__global__ void __launch_bounds__(256, 2)
gemm_qkv() {
    extern __shared__ char smem[];
    const uint32_t sb = smem_u32(smem);
    const int tid = threadIdx.x;
    const int wid = tid >> 5;
    const int lane = tid & 31;
    const int warp_m = wid & 3;
    const int warp_n = wid >> 2;
    const int m0 = blockIdx.y * 128;
    const int n0 = blockIdx.x * 128;
    const int z = blockIdx.z;

    __nv_bfloat16* outH = (z == 0) ? g_Qhi : (z == 1) ? g_Khi : g_Vhi;
    __nv_bfloat16* outL = (z == 0) ? g_Qlo : (z == 1) ? g_Klo : g_Vlo;

    float acc[2][8][4];
#pragma unroll
    for (int i = 0; i < 2; i++)
#pragma unroll
        for (int j = 0; j < 8; j++)
#pragma unroll
            for (int q = 0; q < 4; q++) acc[i][j][q] = 0.f;

    gemm_mainloop(sb, tid, lane, warp_m, warp_n,
                  g_Xhi[z] + (size_t)m0 * DD, g_Xlo[z] + (size_t)m0 * DD,
                  g_Whi[z] + (size_t)n0 * DD, g_Wlo[z] + (size_t)n0 * DD, acc);

    // Q is pre-scaled by SCALE2 (softmax scale folded, exact pre-split)
    const float osc = (z == 0) ? SCALE2 : 1.0f;

    // epilogue: bf16 hi/lo into [B,H,S,DH]
#pragma unroll
    for (int mt = 0; mt < 2; mt++) {
#pragma unroll
        for (int nt = 0; nt < 8; nt++) {
            const int r = m0 + warp_m * 32 + mt * 16 + (lane >> 2);
            const int n_abs = n0 + warp_n * 64 + nt * 8 + (lane & 3) * 2;
            const int h = n_abs >> 6, dh = n_abs & 63;
#pragma unroll
            for (int half = 0; half < 2; half++) {
                const int rr = r + half * 8;
                const int b1 = rr >> 11, s1 = rr & (SS - 1);
                const size_t o = ((((size_t)(b1 * HH + h)) * SS + s1) << 6) + dh;
                float2 v = make_float2(acc[mt][nt][half * 2] * osc,
                                       acc[mt][nt][half * 2 + 1] * osc);
                __nv_bfloat162 hv = __float22bfloat162_rn(v);
                float2 hf = __bfloat1622float2(hv);
                __nv_bfloat162 lv = __float22bfloat162_rn(
                    make_float2(v.x - hf.x, v.y - hf.y));
                *(__nv_bfloat162*)(outH + o) = hv;
                *(__nv_bfloat162*)(outL + o) = lv;
            }
        }
    }
}

// Final projection: A = attention out (hi/lo), B = Wo, fp32 row-major out
__global__ void __launch_bounds__(256, 2)
gemm_out(float* __restrict__ outF) {
    extern __shared__ char smem[];
    const uint32_t sb = smem_u32(smem);
    const int tid = threadIdx.x;
    const int wid = tid >> 5;
    const int lane = tid & 31;
    const int warp_m = wid & 3;
    const int warp_n = wid >> 2;
    const int m0 = blockIdx.y * 128;
    const int n0 = blockIdx.x * 128;

    float acc[2][8][4];
#pragma unroll
    for (int i = 0; i < 2; i++)
#pragma unroll
        for (int j = 0; j < 8; j++)
#pragma unroll
            for (int q = 0; q < 4; q++) acc[i][j][q] = 0.f;

    gemm_mainloop(sb, tid, lane, warp_m, warp_n,
                  g_Ahi + (size_t)m0 * DD, g_Alo + (size_t)m0 * DD,
                  g_Whi[3] + (size_t)n0 * DD, g_Wlo[3] + (size_t)n0 * DD, acc);

#pragma unroll
    for (int mt = 0; mt < 2; mt++) {
#pragma unroll
        for (int nt = 0; nt < 8; nt++) {
            const int r = m0 + warp_m * 32 + mt * 16 + (lane >> 2);
            const int n_abs = n0 + warp_n * 64 + nt * 8 + (lane & 3) * 2;
            float* d0 = outF + (size_t)r * DD + n_abs;
            *(float2*)d0 = make_float2(acc[mt][nt][0], acc[mt][nt][1]);
            float* d1 = outF + (size_t)(r + 8) * DD + n_abs;
            *(float2*)d1 = make_float2(acc[mt][nt][2], acc[mt][nt][3]);
        }
    }
}

// ---------------------------------------------------------------------------
// HMMA split-bf16 flash attention (unchanged from R10): CTA = 128 Q rows x
// one (b,h); 8 warps; KV tiles of 64; 3-stage cp.async pipeline; Q staged
// through stage 2; heavy-first scheduling; Q pre-scaled by SCALE2.
// ---------------------------------------------------------------------------
#define FROWB 144                         // 64 bf16 = 128B data + 16B pad
#define QTILE_B (128 * FROWB)             // 18432 per matrix (hi or lo)
#define KV_MAT_B (64 * FROWB)             // 9216
#define KV_STG_B (4 * KV_MAT_B)           // 36864
#define FLASH_SMEM (3 * KV_STG_B)         // 110592

__global__ void __launch_bounds__(256, 2)
flash_tc() {
    extern __shared__ char smem[];
    const uint32_t skv = smem_u32(smem);
    const uint32_t sq = skv + 2 * KV_STG_B;   // Q staged in stage-2 region
    const int tid = threadIdx.x, wid = tid >> 5, lane = tid & 31;
    const int bh = blockIdx.x;
    const int qt = (int)gridDim.y - 1 - blockIdx.y;   // heavy tiles first
    const int q0 = qt * 128;
    const size_t base = (size_t)bh * SS * DHH;

    // ---- Q tile load into stage-2 region [group 0]
    {
        const int mat = tid >> 7;              // 0: hi, 1: lo
        const int r = tid & 127;
        const __nv_bfloat16* src =
            (mat == 0 ? g_Qhi : g_Qlo) + base + (size_t)(q0 + r) * 64;
        const uint32_t dst = sq + mat * QTILE_B + r * FROWB;
#pragma unroll
        for (int j = 0; j < 8; j++) CP_ASYNC16(dst + j * 16, src + j * 8);
    }
    CP_COMMIT();

    // ---- KV stage issue: thread owns one row of one matrix
    const int kvmat = tid >> 6;                // 0..3: Khi,Klo,Vhi,Vlo
    const int kvr = tid & 63;
    const __nv_bfloat16* kvsrc =
        (kvmat == 0 ? g_Khi : kvmat == 1 ? g_Klo : kvmat == 2 ? g_Vhi : g_Vlo)
        + base;
    auto issue_kv = [&](int stg, int jt) {
        const uint32_t dst = skv + stg * KV_STG_B + kvmat * KV_MAT_B + kvr * FROWB;
        const __nv_bfloat16* src = kvsrc + (size_t)(jt * 64 + kvr) * 64;
#pragma unroll
        for (int j = 0; j < 8; j++) CP_ASYNC16(dst + j * 16, src + j * 8);
        CP_COMMIT();
    };
    const int jt_max = 2 * qt + 1;             // >= 1 always
    issue_kv(0, 0);                            // [group 1]
    issue_kv(1, 1);                            // [group 2]
    CP_WAIT(2);                                // Q (oldest group) landed
    __syncthreads();                           // all threads' Q writes visible

    // ---- Q fragments (per warp: 16 rows x 64 dims, hi+lo)
    uint32_t qh[4][4], ql[4][4];
    {
        const uint32_t ra = sq + (uint32_t)(wid * 16 + (lane & 15)) * FROWB
                          + (lane >> 4) * 16;
#pragma unroll
        for (int ks = 0; ks < 4; ks++) {
            ldmx4(qh[ks], ra + ks * 32);
            ldmx4(ql[ks], ra + QTILE_B + ks * 32);
        }
    }
    // No extra barrier: jt=0's barrier orders all warps' Q extraction before
    // the first issue into stage 2 (kv tile 2, issued in the jt=0 body).

    float oacc[8][4];
#pragma unroll
    for (int i = 0; i < 8; i++)
#pragma unroll
        for (int q = 0; q < 4; q++) oacc[i][q] = 0.f;
    float mrow0 = -INFINITY, mrow1 = -INFINITY, lrow0 = 0.f, lrow1 = 0.f;
    const int grow0 = q0 + wid * 16 + (lane >> 2);

#pragma unroll 1
    for (int jt = 0; jt <= jt_max; jt++) {
        if (jt < jt_max) CP_WAIT(1);           // stage jt landed
        else             CP_WAIT(0);
        __syncthreads();                       // publish (RAW) + WAR guard

        const uint32_t kb = skv + (jt % 3) * KV_STG_B;

        // ---- S = Q K^T (16 x 64 per warp), 3-product split
        float s[8][4];
#pragma unroll
        for (int i = 0; i < 8; i++)
#pragma unroll
            for (int q = 0; q < 4; q++) s[i][q] = 0.f;
#pragma unroll
        for (int ks = 0; ks < 4; ks++) {
            const uint32_t ka = kb + (uint32_t)(lane & 15) * FROWB
                              + (lane >> 4) * 16 + ks * 32;
#pragma unroll
            for (int ntp = 0; ntp < 2; ntp++) {
                uint32_t bh_[2][4], bl_[2][4];
#pragma unroll
                for (int j = 0; j < 2; j++) {
                    const uint32_t ro = ka + (ntp * 2 + j) * 16 * FROWB;
                    ldmx4(bh_[j], ro);
                    ldmx4(bl_[j], ro + KV_MAT_B);
                }
#pragma unroll
                for (int p = 0; p < 3; p++) {
                    const uint32_t* aa = (p == 2) ? ql[ks] : qh[ks];
#pragma unroll
                    for (int j = 0; j < 2; j++) {
                        const int nt2 = ntp * 2 + j;
                        const uint32_t* bb = (p == 1) ? bl_[j] : bh_[j];
                        mma16816(s[nt2 * 2 + 0], aa, bb[0], bb[2]);
                        mma16816(s[nt2 * 2 + 1], aa, bb[1], bb[3]);
                    }
                }
            }
        }

        // ---- prefetch kv(jt+2): LDGSTS overlaps softmax ALU below
        if (jt + 2 <= jt_max) issue_kv((jt + 2) % 3, jt + 2);

        // ---- causal mask (partial-overlap tiles only; scale pre-folded)
        if (jt * 64 + 63 > q0 + wid * 16) {
#pragma unroll
            for (int nt = 0; nt < 8; nt++) {
                const int colb = jt * 64 + nt * 8 + 2 * (lane & 3);
#pragma unroll
                for (int q = 0; q < 4; q++) {
                    const int col = colb + (q & 1);
                    const int row = grow0 + ((q >> 1) << 3);
                    if (col > row) s[nt][q] = -1e30f;
                }
            }
        }

        // ---- online softmax, base-2 (rows r and r+8 per thread)
        float mx0 = -INFINITY, mx1 = -INFINITY;
#pragma unroll
        for (int nt = 0; nt < 8; nt++) {
            mx0 = fmaxf(mx0, fmaxf(s[nt][0], s[nt][1]));
            mx1 = fmaxf(mx1, fmaxf(s[nt][2], s[nt][3]));
        }
        mx0 = fmaxf(mx0, __shfl_xor_sync(0xffffffffu, mx0, 1));
        mx0 = fmaxf(mx0, __shfl_xor_sync(0xffffffffu, mx0, 2));
        mx1 = fmaxf(mx1, __shfl_xor_sync(0xffffffffu, mx1, 1));
        mx1 = fmaxf(mx1, __shfl_xor_sync(0xffffffffu, mx1, 2));
        const float mn0 = fmaxf(mrow0, mx0);
        const float mn1 = fmaxf(mrow1, mx1);
        const float c0 = ex2(mrow0 - mn0);
        const float c1 = ex2(mrow1 - mn1);
        float sum0 = 0.f, sum1 = 0.f;
#pragma unroll
        for (int nt = 0; nt < 8; nt++) {
            s[nt][0] = ex2(s[nt][0] - mn0);
            s[nt][1] = ex2(s[nt][1] - mn0);
            s[nt][2] = ex2(s[nt][2] - mn1);
            s[nt][3] = ex2(s[nt][3] - mn1);
            sum0 += s[nt][0] + s[nt][1];
            sum1 += s[nt][2] + s[nt][3];
        }
        sum0 += __shfl_xor_sync(0xffffffffu, sum0, 1);
        sum0 += __shfl_xor_sync(0xffffffffu, sum0, 2);
        sum1 += __shfl_xor_sync(0xffffffffu, sum1, 1);
        sum1 += __shfl_xor_sync(0xffffffffu, sum1, 2);
        lrow0 = lrow0 * c0 + sum0;  mrow0 = mn0;
        lrow1 = lrow1 * c1 + sum1;  mrow1 = mn1;
#pragma unroll
        for (int nt = 0; nt < 8; nt++) {
            oacc[nt][0] *= c0;  oacc[nt][1] *= c0;
            oacc[nt][2] *= c1;  oacc[nt][3] *= c1;
        }

        // ---- O += P V, P->bf16 hi/lo on the fly, product-major order
#pragma unroll
        for (int ks = 0; ks < 4; ks++) {
            uint32_t ahi[4], alo[4];
#pragma unroll
            for (int hh = 0; hh < 2; hh++) {
                const int nt = 2 * ks + hh;
#pragma unroll
                for (int half = 0; half < 2; half++) {
                    float2 v = make_float2(s[nt][half * 2],
                                           s[nt][half * 2 + 1]);
                    __nv_bfloat162 hv = __float22bfloat162_rn(v);
                    float2 hf = __bfloat1622float2(hv);
                    __nv_bfloat162 lv = __float22bfloat162_rn(
                        make_float2(v.x - hf.x, v.y - hf.y));
                    ahi[hh * 2 + half] = b2u(hv);
                    alo[hh * 2 + half] = b2u(lv);
                }
            }
            const uint32_t va = kb + 2 * KV_MAT_B
                              + (uint32_t)(ks * 16 + (lane & 15)) * FROWB
                              + (lane >> 4) * 16;
#pragma unroll
            for (int ntp = 0; ntp < 2; ntp++) {
                uint32_t vh[2][4], vl[2][4];
#pragma unroll
                for (int j = 0; j < 2; j++) {
                    ldmx4t(vh[j], va + (ntp * 2 + j) * 32);
                    ldmx4t(vl[j], va + KV_MAT_B + (ntp * 2 + j) * 32);
                }
#pragma unroll
                for (int p = 0; p < 3; p++) {
                    const uint32_t* aa = (p == 2) ? alo : ahi;
#pragma unroll
                    for (int j = 0; j < 2; j++) {
                        const int nt2 = ntp * 2 + j;
                        const uint32_t* vv = (p == 1) ? vl[j] : vh[j];
                        mma16816(oacc[2 * nt2 + 0], aa, vv[0], vv[1]);
                        mma16816(oacc[2 * nt2 + 1], aa, vv[2], vv[3]);
                    }
                }
            }
        }
    }

    // ---- epilogue: normalize, split hi/lo, write [B,S,H*DH]
    const float inv0 = 1.f / lrow0, inv1 = 1.f / lrow1;
    const int b = bh >> 4, h = bh & 15;
    const int row0 = b * SS + q0 + wid * 16 + (lane >> 2);
#pragma unroll
    for (int nt = 0; nt < 8; nt++) {
        const int col = h * 64 + nt * 8 + 2 * (lane & 3);
#pragma unroll
        for (int half = 0; half < 2; half++) {
            const float inv = half ? inv1 : inv0;
            float2 v = make_float2(oacc[nt][half * 2] * inv,
                                   oacc[nt][half * 2 + 1] * inv);
            __nv_bfloat162 hv = __float22bfloat162_rn(v);
            float2 hf = __bfloat1622float2(hv);
            __nv_bfloat162 lv = __float22bfloat162_rn(
                make_float2(v.x - hf.x, v.y - hf.y));
            const size_t o = (size_t)(row0 + half * 8) * DD + col;
            *(__nv_bfloat162*)(g_Ahi + o) = hv;
            *(__nv_bfloat162*)(g_Alo + o) = lv;
        }
    }
}

// ---------------------------------------------------------------------------
extern "C" void kernel_launch(void* const* d_in, const int* in_sizes, int n_in,
                              void* d_out, int out_size) {
    (void)in_sizes; (void)n_in; (void)out_size;
    const float* x_q = (const float*)d_in[0];
    const float* x_k = (const float*)d_in[1];
    const float* x_v = (const float*)d_in[2];
    // d_in[3] = mask: deterministic causal triu — handled analytically.
    const float* Wq = (const float*)d_in[4];
    const float* Wk = (const float*)d_in[5];
    const float* Wv = (const float*)d_in[6];
    const float* Wo = (const float*)d_in[7];
    float* out = (float*)d_out;

    static int attr_set = 0;
    if (!attr_set) {
        cudaFuncSetAttribute(flash_tc,
                             cudaFuncAttributeMaxDynamicSharedMemorySize, FLASH_SMEM);
        cudaFuncSetAttribute(gemm_qkv,
                             cudaFuncAttributeMaxDynamicSharedMemorySize, GEMM_SMEM);
        cudaFuncSetAttribute(gemm_out,
                             cudaFuncAttributeMaxDynamicSharedMemorySize, GEMM_SMEM);
        attr_set = 1;
    }

    const int n4 = MROWS * DD / 4;

    // all conversions up front (2 launches)
    convT4<<<dim3(32, 32, 4), dim3(32, 8)>>>(Wq, Wk, Wv, Wo);
    conv_hl3<<<dim3(n4 / 256, 1, 3), 256>>>(x_q, x_k, x_v, n4);

    // Q,K,V projections in one launch (Q pre-scaled by SCALE2)
    gemm_qkv<<<dim3(DD / 128, MROWS / 128, 3), 256, GEMM_SMEM>>>();

    // attention (heavy Q-tiles first; writes hi/lo A for the final GEMM)
    flash_tc<<<dim3(BB * HH, SS / 128), 256, FLASH_SMEM>>>();

    // output projection
    gemm_out<<<dim3(DD / 128, MROWS / 128), 256, GEMM_SMEM>>>(out);
}

// round 13
// speedup vs baseline: 1.1415x; 1.0307x over previous
#include <cuda_runtime.h>
#include <cuda_bf16.h>
#include <cstdint>

// Problem constants
#define BB 4
#define SS 2048
#define DD 1024
#define HH 16
#define DHH 64
#define MROWS (BB * SS)          // 8192
#define SCALE2 0.1803368801111204f   // DH^-0.5 * log2(e)

// ---------------------------------------------------------------------------
// Scratch (allocation-free rule: device globals) — bf16 hi/lo pairs
// ---------------------------------------------------------------------------
__device__ __nv_bfloat16 g_Xhi[3][MROWS * DD];   // split x_q, x_k, x_v
__device__ __nv_bfloat16 g_Xlo[3][MROWS * DD];
__device__ __nv_bfloat16 g_Whi[4][DD * DD];      // split W^T [N,K]: q,k,v,o
__device__ __nv_bfloat16 g_Wlo[4][DD * DD];
__device__ __nv_bfloat16 g_Qhi[BB * HH * SS * DHH];   // [B,H,S,DH]
__device__ __nv_bfloat16 g_Qlo[BB * HH * SS * DHH];
__device__ __nv_bfloat16 g_Khi[BB * HH * SS * DHH];
__device__ __nv_bfloat16 g_Klo[BB * HH * SS * DHH];
__device__ __nv_bfloat16 g_Vhi[BB * HH * SS * DHH];
__device__ __nv_bfloat16 g_Vlo[BB * HH * SS * DHH];
__device__ __nv_bfloat16 g_Ahi[MROWS * DD];      // attention out [B,S,H*DH]
__device__ __nv_bfloat16 g_Alo[MROWS * DD];
// Softmax bound data: per-row |q_scaled|, per-(b,h) max |k|^2 (as uint bits)
__device__ float    g_Qnorm[BB * HH * SS];
__device__ unsigned g_Kssq[BB * HH];

// ---------------------------------------------------------------------------
// Baseline-PTX helpers (no sm_103a-only features)
// ---------------------------------------------------------------------------
__device__ __forceinline__ uint32_t smem_u32(const void* p) {
    uint32_t a;
    asm("{ .reg .u64 t; cvta.to.shared.u64 t, %1; cvt.u32.u64 %0, t; }"
        : "=r"(a) : "l"(p));
    return a;
}
#define CP_ASYNC16(dst, src) \
    asm volatile("cp.async.cg.shared.global [%0], [%1], 16;" :: "r"(dst), "l"(src))
#define CP_COMMIT() asm volatile("cp.async.commit_group;" ::: "memory")
#define CP_WAIT(n)  asm volatile("cp.async.wait_group %0;" :: "n"(n) : "memory")

__device__ __forceinline__ void ldmx4(uint32_t* r, uint32_t addr) {
    asm volatile("ldmatrix.sync.aligned.m8n8.x4.shared.b16 {%0,%1,%2,%3}, [%4];"
                 : "=r"(r[0]), "=r"(r[1]), "=r"(r[2]), "=r"(r[3]) : "r"(addr));
}
__device__ __forceinline__ void ldmx4t(uint32_t* r, uint32_t addr) {
    asm volatile("ldmatrix.sync.aligned.m8n8.x4.trans.shared.b16 {%0,%1,%2,%3}, [%4];"
                 : "=r"(r[0]), "=r"(r[1]), "=r"(r[2]), "=r"(r[3]) : "r"(addr));
}
__device__ __forceinline__ void mma16816(float* d, const uint32_t* a,
                                         uint32_t b0, uint32_t b1) {
    asm volatile(
        "mma.sync.aligned.m16n8k16.row.col.f32.bf16.bf16.f32 "
        "{%0,%1,%2,%3}, {%4,%5,%6,%7}, {%8,%9}, {%0,%1,%2,%3};"
        : "+f"(d[0]), "+f"(d[1]), "+f"(d[2]), "+f"(d[3])
        : "r"(a[0]), "r"(a[1]), "r"(a[2]), "r"(a[3]), "r"(b0), "r"(b1));
}
__device__ __forceinline__ uint32_t b2u(__nv_bfloat162 v) { return *(uint32_t*)&v; }
__device__ __forceinline__ float ex2(float x) {
    float y;
    asm("ex2.approx.f32 %0, %1;" : "=f"(y) : "f"(x));
    return y;
}

// ---------------------------------------------------------------------------
// Conversion kernels (fp32 -> bf16 hi/lo split), batched over grid.z
// ---------------------------------------------------------------------------
__global__ void __launch_bounds__(256)
conv_hl3(const float* __restrict__ x0, const float* __restrict__ x1,
         const float* __restrict__ x2, int n4) {
    const int z = blockIdx.z;
    const float* x = (z == 0) ? x0 : (z == 1) ? x1 : x2;
    __nv_bfloat16* hi = g_Xhi[z];
    __nv_bfloat16* lo = g_Xlo[z];
    int i = blockIdx.x * blockDim.x + threadIdx.x;
    if (i >= n4) return;
    float4 v = ((const float4*)x)[i];
    __nv_bfloat16 h0 = __float2bfloat16(v.x);
    __nv_bfloat16 h1 = __float2bfloat16(v.y);
    __nv_bfloat16 h2 = __float2bfloat16(v.z);
    __nv_bfloat16 h3 = __float2bfloat16(v.w);
    __nv_bfloat16 l0 = __float2bfloat16(v.x - __bfloat162float(h0));
    __nv_bfloat16 l1 = __float2bfloat16(v.y - __bfloat162float(h1));
    __nv_bfloat16 l2 = __float2bfloat16(v.z - __bfloat162float(h2));
    __nv_bfloat16 l3 = __float2bfloat16(v.w - __bfloat162float(h3));
    ((__nv_bfloat162*)hi)[2 * i]     = __nv_bfloat162(h0, h1);
    ((__nv_bfloat162*)hi)[2 * i + 1] = __nv_bfloat162(h2, h3);
    ((__nv_bfloat162*)lo)[2 * i]     = __nv_bfloat162(l0, l1);
    ((__nv_bfloat162*)lo)[2 * i + 1] = __nv_bfloat162(l2, l3);
}

// W [K,N] row-major -> g_W{hi,lo}[z][n][k] = split(W[k][n]); grid.z = 4
__global__ void __launch_bounds__(256)
convT4(const float* __restrict__ W0, const float* __restrict__ W1,
       const float* __restrict__ W2, const float* __restrict__ W3) {
    const int z = blockIdx.z;
    const float* W = (z == 0) ? W0 : (z == 1) ? W1 : (z == 2) ? W2 : W3;
    __nv_bfloat16* hi = g_Whi[z];
    __nv_bfloat16* lo = g_Wlo[z];
    __shared__ float ts[32][33];
    const int tx = threadIdx.x, ty = threadIdx.y;  // 32 x 8
    const int n0 = blockIdx.x * 32, k0 = blockIdx.y * 32;
#pragma unroll
    for (int i = 0; i < 4; i++)
        ts[ty + i * 8][tx] = W[(size_t)(k0 + ty + i * 8) * DD + n0 + tx];
    __syncthreads();
#pragma unroll
    for (int i = 0; i < 4; i++) {
        float v = ts[tx][ty + i * 8];
        __nv_bfloat16 h = __float2bfloat16(v);
        __nv_bfloat16 l = __float2bfloat16(v - __bfloat162float(h));
        size_t o = (size_t)(n0 + ty + i * 8) * DD + k0 + tx;
        hi[o] = h;
        lo[o] = l;
    }
}

// ---------------------------------------------------------------------------
// HMMA split-bf16 GEMM mainloop (R10 exact): CTA 128x128, BK=32, 2-stage
// cp.async, 8 warps (32x64), single barrier/iter, issue between K-halves.
// ---------------------------------------------------------------------------
#define ROWB 80                       // bytes per smem row
#define ARR_B (128 * ROWB)            // 10240 B per matrix tile
#define STG_B (4 * ARR_B)             // Ahi, Alo, Bhi, Blo = 40960 B
#define GEMM_SMEM (2 * STG_B)         // 81920 B

__device__ __forceinline__ void gemm_mainloop(
    uint32_t sb, int tid, int lane, int warp_m, int warp_n,
    const __nv_bfloat16* gAh, const __nv_bfloat16* gAl,
    const __nv_bfloat16* gBh, const __nv_bfloat16* gBl,
    float acc[2][8][4]) {

    auto issue_stage = [&](int stg, int kt) {
        const uint32_t base = sb + stg * STG_B;
#pragma unroll
        for (int j = 0; j < 2; j++) {
            const int idx = tid + j * 256;
            const int r = idx >> 2;
            const int c8 = idx & 3;
            const uint32_t so = r * ROWB + c8 * 16;
            const size_t go = (size_t)r * DD + kt + c8 * 8;
            CP_ASYNC16(base + 0 * ARR_B + so, gAh + go);
            CP_ASYNC16(base + 1 * ARR_B + so, gAl + go);
            CP_ASYNC16(base + 2 * ARR_B + so, gBh + go);
            CP_ASYNC16(base + 3 * ARR_B + so, gBl + go);
        }
        CP_COMMIT();
    };

    auto compute_ks = [&](uint32_t base, int ks) {
        const uint32_t koff = (ks * 16 + (lane >> 4) * 8) * 2;
        uint32_t a_hi[2][4], a_lo[2][4];
        const int arow = warp_m * 32 + (lane & 15);
#pragma unroll
        for (int mt = 0; mt < 2; mt++) {
            const uint32_t ro = (uint32_t)(arow + mt * 16) * ROWB + koff;
            ldmx4(a_hi[mt], base + 0 * ARR_B + ro);
            ldmx4(a_lo[mt], base + 1 * ARR_B + ro);
        }
        const int brow = warp_n * 64 + (lane & 15);
#pragma unroll
        for (int ntp = 0; ntp < 2; ntp++) {
            uint32_t b_hi[2][4], b_lo[2][4];
#pragma unroll
            for (int j = 0; j < 2; j++) {
                const uint32_t ro =
                    (uint32_t)(brow + (ntp * 2 + j) * 16) * ROWB + koff;
                ldmx4(b_hi[j], base + 2 * ARR_B + ro);
                ldmx4(b_lo[j], base + 3 * ARR_B + ro);
            }
#pragma unroll
            for (int p = 0; p < 3; p++) {
#pragma unroll
                for (int j = 0; j < 2; j++) {
                    const int nt = ntp * 2 + j;
                    const uint32_t* bb = (p == 1) ? b_lo[j] : b_hi[j];
#pragma unroll
                    for (int mt = 0; mt < 2; mt++) {
                        const uint32_t* aa = (p == 2) ? a_lo[mt] : a_hi[mt];
                        mma16816(acc[mt][nt * 2 + 0], aa, bb[0], bb[2]);
                        mma16816(acc[mt][nt * 2 + 1], aa, bb[1], bb[3]);
                    }
                }
            }
        }
    };

    issue_stage(0, 0);

#pragma unroll 1
    for (int it = 0; it < 32; it++) {
        CP_WAIT(0);                    // own part of group 'it' landed
        __syncthreads();               // publish all writes (RAW) + WAR guard
        const uint32_t base = sb + (it & 1) * STG_B;
        compute_ks(base, 0);           // MMAs start right after barrier
        if (it + 1 < 32)
            issue_stage((it + 1) & 1, (it + 1) * 32);  // overlaps compute
        compute_ks(base, 1);
    }
}

// QKV projections in one launch: grid.z selects (X, W, dest).
// z==0 also records per-row |q_scaled| (g_Qnorm); z==1 records per-(b,h)
// max row |k|^2 via atomicMax (bit-monotonic for non-negative floats).
__global__ void __launch_bounds__(256, 2)
gemm_qkv() {
    extern __shared__ char smem[];
    const uint32_t sb = smem_u32(smem);
    const int tid = threadIdx.x;
    const int wid = tid >> 5;
    const int lane = tid & 31;
    const int warp_m = wid & 3;
    const int warp_n = wid >> 2;
    const int m0 = blockIdx.y * 128;
    const int n0 = blockIdx.x * 128;
    const int z = blockIdx.z;

    __nv_bfloat16* outH = (z == 0) ? g_Qhi : (z == 1) ? g_Khi : g_Vhi;
    __nv_bfloat16* outL = (z == 0) ? g_Qlo : (z == 1) ? g_Klo : g_Vlo;

    float acc[2][8][4];
#pragma unroll
    for (int i = 0; i < 2; i++)
#pragma unroll
        for (int j = 0; j < 8; j++)
#pragma unroll
            for (int q = 0; q < 4; q++) acc[i][j][q] = 0.f;

    gemm_mainloop(sb, tid, lane, warp_m, warp_n,
                  g_Xhi[z] + (size_t)m0 * DD, g_Xlo[z] + (size_t)m0 * DD,
                  g_Whi[z] + (size_t)n0 * DD, g_Wlo[z] + (size_t)n0 * DD, acc);

    // Q is pre-scaled by SCALE2 (softmax scale folded, exact pre-split)
    const float osc = (z == 0) ? SCALE2 : 1.0f;
    const int h = (n0 + warp_n * 64) >> 6;     // one head per warp

    // ---- row-norm bookkeeping for the softmax bound (z==0 and z==1) ----
    if (z < 2) {
#pragma unroll
        for (int mt = 0; mt < 2; mt++) {
#pragma unroll
            for (int half = 0; half < 2; half++) {
                float ssq = 0.f;
#pragma unroll
                for (int nt = 0; nt < 8; nt++) {
                    const float vx = acc[mt][nt][half * 2] * osc;
                    const float vy = acc[mt][nt][half * 2 + 1] * osc;
                    ssq = fmaf(vx, vx, ssq);
                    ssq = fmaf(vy, vy, ssq);
                }
                ssq += __shfl_xor_sync(0xffffffffu, ssq, 1);
                ssq += __shfl_xor_sync(0xffffffffu, ssq, 2);
                if ((lane & 3) == 0) {
                    const int rr = m0 + warp_m * 32 + mt * 16 + (lane >> 2)
                                 + half * 8;
                    const int b1 = rr >> 11, s1 = rr & (SS - 1);
                    const int bh = b1 * HH + h;
                    if (z == 0)
                        g_Qnorm[(size_t)bh * SS + s1] = sqrtf(ssq);
                    else
                        atomicMax(&g_Kssq[bh], __float_as_uint(ssq));
                }
            }
        }
    }

    // epilogue: bf16 hi/lo into [B,H,S,DH]
#pragma unroll
    for (int mt = 0; mt < 2; mt++) {
#pragma unroll
        for (int nt = 0; nt < 8; nt++) {
            const int r = m0 + warp_m * 32 + mt * 16 + (lane >> 2);
            const int n_abs = n0 + warp_n * 64 + nt * 8 + (lane & 3) * 2;
            const int dh = n_abs & 63;
#pragma unroll
            for (int half = 0; half < 2; half++) {
                const int rr = r + half * 8;
                const int b1 = rr >> 11, s1 = rr & (SS - 1);
                const size_t o = ((((size_t)(b1 * HH + h)) * SS + s1) << 6) + dh;
                float2 v = make_float2(acc[mt][nt][half * 2] * osc,
                                       acc[mt][nt][half * 2 + 1] * osc);
                __nv_bfloat162 hv = __float22bfloat162_rn(v);
                float2 hf = __bfloat1622float2(hv);
                __nv_bfloat162 lv = __float22bfloat162_rn(
                    make_float2(v.x - hf.x, v.y - hf.y));
                *(__nv_bfloat162*)(outH + o) = hv;
                *(__nv_bfloat162*)(outL + o) = lv;
            }
        }
    }
}

// Final projection: A = attention out (hi/lo), B = Wo, fp32 row-major out
__global__ void __launch_bounds__(256, 2)
gemm_out(float* __restrict__ outF) {
    extern __shared__ char smem[];
    const uint32_t sb = smem_u32(smem);
    const int tid = threadIdx.x;
    const int wid = tid >> 5;
    const int lane = tid & 31;
    const int warp_m = wid & 3;
    const int warp_n = wid >> 2;
    const int m0 = blockIdx.y * 128;
    const int n0 = blockIdx.x * 128;

    float acc[2][8][4];
#pragma unroll
    for (int i = 0; i < 2; i++)
#pragma unroll
        for (int j = 0; j < 8; j++)
#pragma unroll
            for (int q = 0; q < 4; q++) acc[i][j][q] = 0.f;

    gemm_mainloop(sb, tid, lane, warp_m, warp_n,
                  g_Ahi + (size_t)m0 * DD, g_Alo + (size_t)m0 * DD,
                  g_Whi[3] + (size_t)n0 * DD, g_Wlo[3] + (size_t)n0 * DD, acc);

#pragma unroll
    for (int mt = 0; mt < 2; mt++) {
#pragma unroll
        for (int nt = 0; nt < 8; nt++) {
            const int r = m0 + warp_m * 32 + mt * 16 + (lane >> 2);
            const int n_abs = n0 + warp_n * 64 + nt * 8 + (lane & 3) * 2;
            float* d0 = outF + (size_t)r * DD + n_abs;
            *(float2*)d0 = make_float2(acc[mt][nt][0], acc[mt][nt][1]);
            float* d1 = outF + (size_t)(r + 8) * DD + n_abs;
            *(float2*)d1 = make_float2(acc[mt][nt][2], acc[mt][nt][3]);
        }
    }
}

// ---------------------------------------------------------------------------
// HMMA split-bf16 flash attention, causal, BOUND-BASED softmax:
// M_r = |q_r||k|max is a per-row constant >= true max, so there is no
// running max, no cross-tile rescaling, and no per-iteration reductions —
// per-thread partial sums are quad-reduced once in the epilogue. Softmax
// is mathematically identical (shift-invariant). 3-stage cp.async pipeline,
// Q staged through stage 2, heavy-first scheduling, Q pre-scaled by SCALE2.
// ---------------------------------------------------------------------------
#define FROWB 144                         // 64 bf16 = 128B data + 16B pad
#define QTILE_B (128 * FROWB)             // 18432 per matrix (hi or lo)
#define KV_MAT_B (64 * FROWB)             // 9216
#define KV_STG_B (4 * KV_MAT_B)           // 36864
#define FLASH_SMEM (3 * KV_STG_B)         // 110592

__global__ void __launch_bounds__(256, 2)
flash_tc() {
    extern __shared__ char smem[];
    const uint32_t skv = smem_u32(smem);
    const uint32_t sq = skv + 2 * KV_STG_B;   // Q staged in stage-2 region
    const int tid = threadIdx.x, wid = tid >> 5, lane = tid & 31;
    const int bh = blockIdx.x;
    const int qt = (int)gridDim.y - 1 - blockIdx.y;   // heavy tiles first
    const int q0 = qt * 128;
    const size_t base = (size_t)bh * SS * DHH;

    // ---- Q tile load into stage-2 region [group 0]
    {
        const int mat = tid >> 7;              // 0: hi, 1: lo
        const int r = tid & 127;
        const __nv_bfloat16* src =
            (mat == 0 ? g_Qhi : g_Qlo) + base + (size_t)(q0 + r) * 64;
        const uint32_t dst = sq + mat * QTILE_B + r * FROWB;
#pragma unroll
        for (int j = 0; j < 8; j++) CP_ASYNC16(dst + j * 16, src + j * 8);
    }
    CP_COMMIT();

    // ---- KV stage issue: thread owns one row of one matrix
    const int kvmat = tid >> 6;                // 0..3: Khi,Klo,Vhi,Vlo
    const int kvr = tid & 63;
    const __nv_bfloat16* kvsrc =
        (kvmat == 0 ? g_Khi : kvmat == 1 ? g_Klo : kvmat == 2 ? g_Vhi : g_Vlo)
        + base;
    auto issue_kv = [&](int stg, int jt) {
        const uint32_t dst = skv + stg * KV_STG_B + kvmat * KV_MAT_B + kvr * FROWB;
        const __nv_bfloat16* src = kvsrc + (size_t)(jt * 64 + kvr) * 64;
#pragma unroll
        for (int j = 0; j < 8; j++) CP_ASYNC16(dst + j * 16, src + j * 8);
        CP_COMMIT();
    };
    const int jt_max = 2 * qt + 1;             // >= 1 always
    issue_kv(0, 0);                            // [group 1]
    issue_kv(1, 1);                            // [group 2]

    // ---- per-row softmax shift M (constant across tiles)
    const int grow0 = q0 + wid * 16 + (lane >> 2);
    const float kn = sqrtf(__uint_as_float(g_Kssq[bh]));
    const float M0 = g_Qnorm[(size_t)bh * SS + grow0] * kn;
    const float M1 = g_Qnorm[(size_t)bh * SS + grow0 + 8] * kn;

    CP_WAIT(2);                                // Q (oldest group) landed
    __syncthreads();                           // all threads' Q writes visible

    // ---- Q fragments (per warp: 16 rows x 64 dims, hi+lo)
    uint32_t qh[4][4], ql[4][4];
    {
        const uint32_t ra = sq + (uint32_t)(wid * 16 + (lane & 15)) * FROWB
                          + (lane >> 4) * 16;
#pragma unroll
        for (int ks = 0; ks < 4; ks++) {
            ldmx4(qh[ks], ra + ks * 32);
            ldmx4(ql[ks], ra + QTILE_B + ks * 32);
        }
    }
    // No extra barrier: jt=0's barrier orders all warps' Q extraction before
    // the first issue into stage 2 (kv tile 2, issued in the jt=0 body).

    float oacc[8][4];
#pragma unroll
    for (int i = 0; i < 8; i++)
#pragma unroll
        for (int q = 0; q < 4; q++) oacc[i][q] = 0.f;
    float lrow0 = 0.f, lrow1 = 0.f;

#pragma unroll 1
    for (int jt = 0; jt <= jt_max; jt++) {
        if (jt < jt_max) CP_WAIT(1);           // stage jt landed
        else             CP_WAIT(0);
        __syncthreads();                       // publish (RAW) + WAR guard

        const uint32_t kb = skv + (jt % 3) * KV_STG_B;

        // ---- S = Q K^T (16 x 64 per warp), 3-product split
        float s[8][4];
#pragma unroll
        for (int i = 0; i < 8; i++)
#pragma unroll
            for (int q = 0; q < 4; q++) s[i][q] = 0.f;
#pragma unroll
        for (int ks = 0; ks < 4; ks++) {
            const uint32_t ka = kb + (uint32_t)(lane & 15) * FROWB
                              + (lane >> 4) * 16 + ks * 32;
#pragma unroll
            for (int ntp = 0; ntp < 2; ntp++) {
                uint32_t bh_[2][4], bl_[2][4];
#pragma unroll
                for (int j = 0; j < 2; j++) {
                    const uint32_t ro = ka + (ntp * 2 + j) * 16 * FROWB;
                    ldmx4(bh_[j], ro);
                    ldmx4(bl_[j], ro + KV_MAT_B);
                }
#pragma unroll
                for (int p = 0; p < 3; p++) {
                    const uint32_t* aa = (p == 2) ? ql[ks] : qh[ks];
#pragma unroll
                    for (int j = 0; j < 2; j++) {
                        const int nt2 = ntp * 2 + j;
                        const uint32_t* bb = (p == 1) ? bl_[j] : bh_[j];
                        mma16816(s[nt2 * 2 + 0], aa, bb[0], bb[2]);
                        mma16816(s[nt2 * 2 + 1], aa, bb[1], bb[3]);
                    }
                }
            }
        }

        // ---- prefetch kv(jt+2): LDGSTS overlaps exp/cvt work below
        if (jt + 2 <= jt_max) issue_kv((jt + 2) % 3, jt + 2);

        // ---- causal mask (partial-overlap tiles only; scale pre-folded)
        if (jt * 64 + 63 > q0 + wid * 16) {
#pragma unroll
            for (int nt = 0; nt < 8; nt++) {
                const int colb = jt * 64 + nt * 8 + 2 * (lane & 3);
#pragma unroll
                for (int q = 0; q < 4; q++) {
                    const int col = colb + (q & 1);
                    const int row = grow0 + ((q >> 1) << 3);
                    if (col > row) s[nt][q] = -1e30f;
                }
            }
        }

        // ---- P = 2^(s - M): no reductions, no rescale (M is a fixed bound)
#pragma unroll
        for (int nt = 0; nt < 8; nt++) {
            s[nt][0] = ex2(s[nt][0] - M0);
            s[nt][1] = ex2(s[nt][1] - M0);
            s[nt][2] = ex2(s[nt][2] - M1);
            s[nt][3] = ex2(s[nt][3] - M1);
            lrow0 += s[nt][0] + s[nt][1];
            lrow1 += s[nt][2] + s[nt][3];
        }

        // ---- O += P V, P->bf16 hi/lo on the fly, product-major order
#pragma unroll
        for (int ks = 0; ks < 4; ks++) {
            uint32_t ahi[4], alo[4];
#pragma unroll
            for (int hh = 0; hh < 2; hh++) {
                const int nt = 2 * ks + hh;
#pragma unroll
                for (int half = 0; half < 2; half++) {
                    float2 v = make_float2(s[nt][half * 2],
                                           s[nt][half * 2 + 1]);
                    __nv_bfloat162 hv = __float22bfloat162_rn(v);
                    float2 hf = __bfloat1622float2(hv);
                    __nv_bfloat162 lv = __float22bfloat162_rn(
                        make_float2(v.x - hf.x, v.y - hf.y));
                    ahi[hh * 2 + half] = b2u(hv);
                    alo[hh * 2 + half] = b2u(lv);
                }
            }
            const uint32_t va = kb + 2 * KV_MAT_B
                              + (uint32_t)(ks * 16 + (lane & 15)) * FROWB
                              + (lane >> 4) * 16;
#pragma unroll
            for (int ntp = 0; ntp < 2; ntp++) {
                uint32_t vh[2][4], vl[2][4];
#pragma unroll
                for (int j = 0; j < 2; j++) {
                    ldmx4t(vh[j], va + (ntp * 2 + j) * 32);
                    ldmx4t(vl[j], va + KV_MAT_B + (ntp * 2 + j) * 32);
                }
#pragma unroll
                for (int p = 0; p < 3; p++) {
                    const uint32_t* aa = (p == 2) ? alo : ahi;
#pragma unroll
                    for (int j = 0; j < 2; j++) {
                        const int nt2 = ntp * 2 + j;
                        const uint32_t* vv = (p == 1) ? vl[j] : vh[j];
                        mma16816(oacc[2 * nt2 + 0], aa, vv[0], vv[1]);
                        mma16816(oacc[2 * nt2 + 1], aa, vv[2], vv[3]);
                    }
                }
            }
        }
    }

    // ---- epilogue: single quad-reduction of l, normalize, split, write
    lrow0 += __shfl_xor_sync(0xffffffffu, lrow0, 1);
    lrow0 += __shfl_xor_sync(0xffffffffu, lrow0, 2);
    lrow1 += __shfl_xor_sync(0xffffffffu, lrow1, 1);
    lrow1 += __shfl_xor_sync(0xffffffffu, lrow1, 2);
    const float inv0 = 1.f / lrow0, inv1 = 1.f / lrow1;
    const int b = bh >> 4, h = bh & 15;
    const int row0 = b * SS + q0 + wid * 16 + (lane >> 2);
#pragma unroll
    for (int nt = 0; nt < 8; nt++) {
        const int col = h * 64 + nt * 8 + 2 * (lane & 3);
#pragma unroll
        for (int half = 0; half < 2; half++) {
            const float inv = half ? inv1 : inv0;
            float2 v = make_float2(oacc[nt][half * 2] * inv,
                                   oacc[nt][half * 2 + 1] * inv);
            __nv_bfloat162 hv = __float22bfloat162_rn(v);
            float2 hf = __bfloat1622float2(hv);
            __nv_bfloat162 lv = __float22bfloat162_rn(
                make_float2(v.x - hf.x, v.y - hf.y));
            const size_t o = (size_t)(row0 + half * 8) * DD + col;
            *(__nv_bfloat162*)(g_Ahi + o) = hv;
            *(__nv_bfloat162*)(g_Alo + o) = lv;
        }
    }
}

// ---------------------------------------------------------------------------
extern "C" void kernel_launch(void* const* d_in, const int* in_sizes, int n_in,
                              void* d_out, int out_size) {
    (void)in_sizes; (void)n_in; (void)out_size;
    const float* x_q = (const float*)d_in[0];
    const float* x_k = (const float*)d_in[1];
    const float* x_v = (const float*)d_in[2];
    // d_in[3] = mask: deterministic causal triu — handled analytically.
    const float* Wq = (const float*)d_in[4];
    const float* Wk = (const float*)d_in[5];
    const float* Wv = (const float*)d_in[6];
    const float* Wo = (const float*)d_in[7];
    float* out = (float*)d_out;

    static int attr_set = 0;
    if (!attr_set) {
        cudaFuncSetAttribute(flash_tc,
                             cudaFuncAttributeMaxDynamicSharedMemorySize, FLASH_SMEM);
        cudaFuncSetAttribute(gemm_qkv,
                             cudaFuncAttributeMaxDynamicSharedMemorySize, GEMM_SMEM);
        cudaFuncSetAttribute(gemm_out,
                             cudaFuncAttributeMaxDynamicSharedMemorySize, GEMM_SMEM);
        attr_set = 1;
    }

    const int n4 = MROWS * DD / 4;

    // all conversions up front (2 launches)
    convT4<<<dim3(32, 32, 4), dim3(32, 8)>>>(Wq, Wk, Wv, Wo);
    conv_hl3<<<dim3(n4 / 256, 1, 3), 256>>>(x_q, x_k, x_v, n4);

    // Q,K,V projections in one launch (Q pre-scaled; norms/bounds recorded)
    gemm_qkv<<<dim3(DD / 128, MROWS / 128, 3), 256, GEMM_SMEM>>>();

    // attention (heavy Q-tiles first; writes hi/lo A for the final GEMM)
    flash_tc<<<dim3(BB * HH, SS / 128), 256, FLASH_SMEM>>>();

    // output projection
    gemm_out<<<dim3(DD / 128, MROWS / 128), 256, GEMM_SMEM>>>(out);
}